// round 2
// baseline (speedup 1.0000x reference)
#include <cuda_runtime.h>

#define D        128
#define BLK      1024
#define MT       64          // i-rows per CTA
#define JT       64          // j-rows per inner tile
#define THREADS  256
#define XSTR     132         // padded smem row stride (floats): 132/4=33 quad-banks, 33%8=1 -> conflict-free row-strided LDS.128
#define WSTR     64

#define NROWS_MAX 262144
__device__ float g_sq[NROWS_MAX];   // per-row squared norms (scratch, no cudaMalloc allowed)

// ---------------------------------------------------------------------------
// Kernel 1: per-row squared norm. One warp per row, float4 per lane.
// ---------------------------------------------------------------------------
__global__ void sq_kernel(const float4* __restrict__ x, int nrows) {
    int row  = blockIdx.x * (blockDim.x / 32) + (threadIdx.x >> 5);
    int lane = threadIdx.x & 31;
    if (row >= nrows) return;
    float4 v = x[(size_t)row * (D / 4) + lane];
    float s = v.x * v.x + v.y * v.y + v.z * v.z + v.w * v.w;
    #pragma unroll
    for (int o = 16; o; o >>= 1) s += __shfl_xor_sync(0xFFFFFFFFu, s, o);
    if (lane == 0) g_sq[row] = s;
}

// ---------------------------------------------------------------------------
// Kernel 2: fused block self-attention.
// CTA handles MT=64 rows of one 1024-row block; loops over 16 j-tiles.
// GEMM1: S[64][64] in regs (4x4/thread) -> exp -> W in smem.
// GEMM2: acc[64][128] in regs (4x8/thread), K=JT per tile.
// ---------------------------------------------------------------------------
__global__ __launch_bounds__(THREADS, 2)
void attn_kernel(const float* __restrict__ x, float* __restrict__ out) {
    extern __shared__ float smem[];
    float* Xi = smem;                       // MT * XSTR
    float* Xj = Xi + MT * XSTR;             // JT * XSTR
    float* Ws = Xj + JT * XSTR;             // MT * WSTR

    const int tid = threadIdx.x;
    const int itile = blockIdx.x;                 // global i-tile index
    const int blk   = itile / (BLK / MT);         // 1024-row block index
    const int isub  = itile % (BLK / MT);

    const float* xblock = x + (size_t)blk * BLK * D;
    const float* xi     = xblock + (size_t)isub * MT * D;

    // ---- load Xi tile (64 x 128) into smem, float4 coalesced ----
    #pragma unroll
    for (int q = tid; q < MT * (D / 4); q += THREADS) {
        int row = q / (D / 4);
        int col = q % (D / 4);
        float4 v = ((const float4*)xi)[row * (D / 4) + col];
        *(float4*)&Xi[row * XSTR + col * 4] = v;
    }

    // GEMM1 mapping: interleaved ownership for conflict-free B loads
    const int ty = tid / 16;     // 0..15 : i-rows  ty + 16*r
    const int tx = tid % 16;     // 0..15 : j-cols  tx + 16*c
    // GEMM2 mapping: rows r2*4+rr, cols c2*8+cc
    const int r2 = tid / 16;
    const int c2 = tid % 16;

    float sqi[4];
    #pragma unroll
    for (int r = 0; r < 4; r++)
        sqi[r] = g_sq[(size_t)blk * BLK + isub * MT + ty + 16 * r];

    float acc[4][8];
    #pragma unroll
    for (int r = 0; r < 4; r++)
        #pragma unroll
        for (int c = 0; c < 8; c++) acc[r][c] = 0.0f;

    const float INV = 1.0f / (2.0f * (D / 10.0f));   // 1/25.6

    for (int jt = 0; jt < BLK / JT; ++jt) {
        __syncthreads();   // protect Xj/Ws from previous iteration's readers

        // ---- load Xj tile ----
        const float* xj = xblock + (size_t)jt * JT * D;
        #pragma unroll
        for (int q = tid; q < JT * (D / 4); q += THREADS) {
            int row = q / (D / 4);
            int col = q % (D / 4);
            float4 v = ((const float4*)xj)[row * (D / 4) + col];
            *(float4*)&Xj[row * XSTR + col * 4] = v;
        }
        float sqj[4];
        #pragma unroll
        for (int c = 0; c < 4; c++)
            sqj[c] = g_sq[(size_t)blk * BLK + jt * JT + tx + 16 * c];
        __syncthreads();

        // ---- GEMM1: S = Xi . Xj^T  (K = 128) ----
        float s[4][4];
        #pragma unroll
        for (int r = 0; r < 4; r++)
            #pragma unroll
            for (int c = 0; c < 4; c++) s[r][c] = 0.0f;

        #pragma unroll 4
        for (int k = 0; k < D; k += 4) {
            float4 a[4], b[4];
            #pragma unroll
            for (int r = 0; r < 4; r++)
                a[r] = *(const float4*)&Xi[(ty + 16 * r) * XSTR + k];
            #pragma unroll
            for (int c = 0; c < 4; c++)
                b[c] = *(const float4*)&Xj[(tx + 16 * c) * XSTR + k];
            #pragma unroll
            for (int r = 0; r < 4; r++)
                #pragma unroll
                for (int c = 0; c < 4; c++) {
                    s[r][c] += a[r].x * b[c].x;
                    s[r][c] += a[r].y * b[c].y;
                    s[r][c] += a[r].z * b[c].z;
                    s[r][c] += a[r].w * b[c].w;
                }
        }

        // ---- epilogue: w = exp(-max(d2,0)/25.6), scatter to smem W ----
        #pragma unroll
        for (int r = 0; r < 4; r++)
            #pragma unroll
            for (int c = 0; c < 4; c++) {
                float d2 = sqi[r] + sqj[c] - 2.0f * s[r][c];
                d2 = fmaxf(d2, 0.0f);
                Ws[(ty + 16 * r) * WSTR + (tx + 16 * c)] = __expf(-d2 * INV);
            }
        __syncthreads();

        // ---- GEMM2: acc += W . Xj  (K = 64) ----
        #pragma unroll 4
        for (int k = 0; k < JT; k += 4) {
            float4 wv[4];
            #pragma unroll
            for (int rr = 0; rr < 4; rr++)
                wv[rr] = *(const float4*)&Ws[(r2 * 4 + rr) * WSTR + k];
            float4 xa[4], xb[4];
            #pragma unroll
            for (int kk = 0; kk < 4; kk++) {
                xa[kk] = *(const float4*)&Xj[(k + kk) * XSTR + c2 * 8];
                xb[kk] = *(const float4*)&Xj[(k + kk) * XSTR + c2 * 8 + 4];
            }
            #pragma unroll
            for (int rr = 0; rr < 4; rr++) {
                float w0 = wv[rr].x, w1 = wv[rr].y, w2 = wv[rr].z, w3 = wv[rr].w;
                acc[rr][0] += w0 * xa[0].x + w1 * xa[1].x + w2 * xa[2].x + w3 * xa[3].x;
                acc[rr][1] += w0 * xa[0].y + w1 * xa[1].y + w2 * xa[2].y + w3 * xa[3].y;
                acc[rr][2] += w0 * xa[0].z + w1 * xa[1].z + w2 * xa[2].z + w3 * xa[3].z;
                acc[rr][3] += w0 * xa[0].w + w1 * xa[1].w + w2 * xa[2].w + w3 * xa[3].w;
                acc[rr][4] += w0 * xb[0].x + w1 * xb[1].x + w2 * xb[2].x + w3 * xb[3].x;
                acc[rr][5] += w0 * xb[0].y + w1 * xb[1].y + w2 * xb[2].y + w3 * xb[3].y;
                acc[rr][6] += w0 * xb[0].z + w1 * xb[1].z + w2 * xb[2].z + w3 * xb[3].z;
                acc[rr][7] += w0 * xb[0].w + w1 * xb[1].w + w2 * xb[2].w + w3 * xb[3].w;
            }
        }
    }

    // ---- write out, scaled by 1/BLK ----
    const float scale = 1.0f / (float)BLK;
    float* orow = out + ((size_t)blk * BLK + (size_t)isub * MT) * D;
    #pragma unroll
    for (int rr = 0; rr < 4; rr++) {
        float4 o0, o1;
        o0.x = acc[rr][0] * scale; o0.y = acc[rr][1] * scale;
        o0.z = acc[rr][2] * scale; o0.w = acc[rr][3] * scale;
        o1.x = acc[rr][4] * scale; o1.y = acc[rr][5] * scale;
        o1.z = acc[rr][6] * scale; o1.w = acc[rr][7] * scale;
        *(float4*)&orow[(r2 * 4 + rr) * D + c2 * 8]     = o0;
        *(float4*)&orow[(r2 * 4 + rr) * D + c2 * 8 + 4] = o1;
    }
}

// ---------------------------------------------------------------------------
extern "C" void kernel_launch(void* const* d_in, const int* in_sizes, int n_in,
                              void* d_out, int out_size) {
    const float* x = (const float*)d_in[0];
    float* out = (float*)d_out;
    const int nrows = in_sizes[0] / D;          // 262144

    // per-row squared norms
    {
        int warps_per_blk = THREADS / 32;
        int grid = (nrows + warps_per_blk - 1) / warps_per_blk;
        sq_kernel<<<grid, THREADS>>>((const float4*)x, nrows);
    }

    // fused attention
    {
        const int smem_bytes = (MT * XSTR + JT * XSTR + MT * WSTR) * (int)sizeof(float);
        static bool attr_set = false;
        if (!attr_set) {
            cudaFuncSetAttribute(attn_kernel,
                                 cudaFuncAttributeMaxDynamicSharedMemorySize,
                                 smem_bytes);
            attr_set = true;
        }
        int grid = nrows / MT;                  // 4096 CTAs
        attn_kernel<<<grid, THREADS, smem_bytes>>>(x, out);
    }
}

// round 4
// speedup vs baseline: 3.6085x; 3.6085x over previous
#include <cuda_runtime.h>
#include <cuda_bf16.h>
#include <cstdint>

#define D        128
#define BLK      1024
#define THREADS  256
#define INVC     (1.0f / 25.6f)

#define RSB      272                     // smem row stride in bytes (136 bf16): 17x16B -> LDSM conflict-free
#define OFF_SQI  0
#define OFF_SQJ  512
#define OFF_XIH  1024
#define OFF_XIL  (OFF_XIH + 128 * RSB)
#define OFF_XJH  (OFF_XIL + 128 * RSB)
#define OFF_XJL  (OFF_XJH + 128 * RSB)
#define SM_TOTAL (OFF_XJL + 128 * RSB)   // 140288 B

// ---------------- PTX helpers (base ISA only — no tcgen05) ----------------
__device__ __forceinline__ uint32_t smem_u32(const void* p) {
    uint32_t a;
    asm("{ .reg .u64 t; cvta.to.shared.u64 t, %1; cvt.u32.u64 %0, t; }" : "=r"(a) : "l"(p));
    return a;
}
__device__ __forceinline__ void ldsm4(uint32_t r[4], uint32_t addr) {
    asm volatile("ldmatrix.sync.aligned.m8n8.x4.shared.b16 {%0,%1,%2,%3}, [%4];"
                 : "=r"(r[0]), "=r"(r[1]), "=r"(r[2]), "=r"(r[3]) : "r"(addr));
}
__device__ __forceinline__ void ldsm4t(uint32_t r[4], uint32_t addr) {
    asm volatile("ldmatrix.sync.aligned.m8n8.x4.trans.shared.b16 {%0,%1,%2,%3}, [%4];"
                 : "=r"(r[0]), "=r"(r[1]), "=r"(r[2]), "=r"(r[3]) : "r"(addr));
}
__device__ __forceinline__ void mma16816(float c[4], const uint32_t a[4],
                                         uint32_t b0, uint32_t b1) {
    asm volatile("mma.sync.aligned.m16n8k16.row.col.f32.bf16.bf16.f32 "
                 "{%0,%1,%2,%3}, {%4,%5,%6,%7}, {%8,%9}, {%0,%1,%2,%3};"
                 : "+f"(c[0]), "+f"(c[1]), "+f"(c[2]), "+f"(c[3])
                 : "r"(a[0]), "r"(a[1]), "r"(a[2]), "r"(a[3]), "r"(b0), "r"(b1));
}
__device__ __forceinline__ uint32_t bf2u(__nv_bfloat162 h) {
    return *reinterpret_cast<uint32_t*>(&h);
}

// ---------------------------------------------------------------------------
// Load one 128x128 fp32 tile -> bf16 hi/lo smem tiles + per-row sq norms.
// Warp w owns rows [16w, 16w+16); lane l owns cols [4l, 4l+4).
// ---------------------------------------------------------------------------
__device__ __forceinline__ void load_tile(const float4* __restrict__ src,
                                          char* hiT, char* loT, float* sqv,
                                          int wid, int l) {
    #pragma unroll
    for (int rr = 0; rr < 16; ++rr) {
        int row = wid * 16 + rr;
        float4 v = __ldg(&src[row * 32 + l]);
        float s = v.x * v.x + v.y * v.y + v.z * v.z + v.w * v.w;
        #pragma unroll
        for (int o = 16; o; o >>= 1) s += __shfl_xor_sync(0xFFFFFFFFu, s, o);
        if (l == 0) sqv[row] = s;
        __nv_bfloat162 h01 = __floats2bfloat162_rn(v.x, v.y);
        __nv_bfloat162 h23 = __floats2bfloat162_rn(v.z, v.w);
        float2 f01 = __bfloat1622float2(h01);
        float2 f23 = __bfloat1622float2(h23);
        __nv_bfloat162 g01 = __floats2bfloat162_rn(v.x - f01.x, v.y - f01.y);
        __nv_bfloat162 g23 = __floats2bfloat162_rn(v.z - f23.x, v.w - f23.y);
        *(uint2*)(hiT + row * RSB + l * 8) = make_uint2(bf2u(h01), bf2u(h23));
        *(uint2*)(loT + row * RSB + l * 8) = make_uint2(bf2u(g01), bf2u(g23));
    }
}

// ---------------------------------------------------------------------------
// Fused block self-attention on HMMA (mma.sync bf16, 3-combo split).
// CTA = 128 i-rows of one 1024-row block; 8 j-tiles of 128.
// ---------------------------------------------------------------------------
__global__ __launch_bounds__(THREADS, 1)
void attn_kernel(const float* __restrict__ x, float* __restrict__ out) {
    extern __shared__ char sm[];
    const uint32_t sb = smem_u32(sm);
    float* sqi = (float*)(sm + OFF_SQI);
    float* sqj = (float*)(sm + OFF_SQJ);

    const int tid = threadIdx.x;
    const int wid = tid >> 5;
    const int l   = tid & 31;
    const int cta  = blockIdx.x;
    const int blkI = cta >> 3, isub = cta & 7;
    const size_t rowbase = (size_t)blkI * BLK;

    // per-lane ldmatrix address offsets (within a tile)
    const int rowA = (l & 7) + ((l >> 3) & 1) * 8;   // A-style: 0-7,8-15 | +16B col
    const int colA = (l >> 4);
    const int rowB = (l & 7) + ((l >> 4) << 3);      // B-style: 0-7 | +16B col, then 8-15
    const int colB = (l >> 3) & 1;
    const uint32_t offA  = (uint32_t)((16 * wid + rowA) * RSB + colA * 16); // GEMM1 A (Xi rows of this warp)
    const uint32_t offB1 = (uint32_t)(rowB * RSB + colB * 16);              // GEMM1 B (Xj, non-trans)
    const uint32_t offB2 = (uint32_t)(rowA * RSB + colA * 16);              // GEMM2 B (Xj, trans)

    // ---- Xi tile + sqi (once) ----
    load_tile((const float4*)(x + (rowbase + (size_t)isub * 128) * D),
              sm + OFF_XIH, sm + OFF_XIL, sqi, wid, l);
    __syncthreads();
    const float sqi0 = sqi[16 * wid + (l >> 2)];
    const float sqi1 = sqi[16 * wid + (l >> 2) + 8];

    float acc2[16][4];
    #pragma unroll
    for (int n = 0; n < 16; ++n)
        #pragma unroll
        for (int c = 0; c < 4; ++c) acc2[n][c] = 0.0f;

    for (int jt = 0; jt < 8; ++jt) {
        __syncthreads();   // all warps done reading previous Xj
        load_tile((const float4*)(x + (rowbase + (size_t)jt * 128) * D),
                  sm + OFF_XJH, sm + OFF_XJL, sqj, wid, l);
        __syncthreads();

        // ---- GEMM1: S = Xi . Xj^T  (hi*hi + hi*lo + lo*hi) ----
        float acc1[16][4];
        #pragma unroll
        for (int n = 0; n < 16; ++n)
            #pragma unroll
            for (int c = 0; c < 4; ++c) acc1[n][c] = 0.0f;

        #pragma unroll
        for (int ks = 0; ks < 8; ++ks) {
            uint32_t ah[4], al[4];
            ldsm4(ah, sb + OFF_XIH + offA + ks * 32);
            ldsm4(al, sb + OFF_XIL + offA + ks * 32);
            #pragma unroll
            for (int np = 0; np < 8; ++np) {
                uint32_t bh[4], bl[4];
                ldsm4(bh, sb + OFF_XJH + offB1 + np * (16 * RSB) + ks * 32);
                ldsm4(bl, sb + OFF_XJL + offB1 + np * (16 * RSB) + ks * 32);
                mma16816(acc1[2 * np],     ah, bh[0], bh[1]);
                mma16816(acc1[2 * np],     ah, bl[0], bl[1]);
                mma16816(acc1[2 * np],     al, bh[0], bh[1]);
                mma16816(acc1[2 * np + 1], ah, bh[2], bh[3]);
                mma16816(acc1[2 * np + 1], ah, bl[2], bl[3]);
                mma16816(acc1[2 * np + 1], al, bh[2], bh[3]);
            }
        }

        // ---- epilogue: w = exp(-max(d2,0)/25.6); split; build A-frags in regs ----
        uint32_t whi[8][4], wlo[8][4];
        #pragma unroll
        for (int ks = 0; ks < 8; ++ks) {
            #pragma unroll
            for (int half = 0; half < 2; ++half) {
                const int nt = 2 * ks + half;
                float2 sj = *(float2*)&sqj[nt * 8 + (l & 3) * 2];
                float w0 = __expf(-fmaxf(sqi0 + sj.x - 2.0f * acc1[nt][0], 0.0f) * INVC);
                float w1 = __expf(-fmaxf(sqi0 + sj.y - 2.0f * acc1[nt][1], 0.0f) * INVC);
                float w2 = __expf(-fmaxf(sqi1 + sj.x - 2.0f * acc1[nt][2], 0.0f) * INVC);
                float w3 = __expf(-fmaxf(sqi1 + sj.y - 2.0f * acc1[nt][3], 0.0f) * INVC);
                __nv_bfloat162 h01 = __floats2bfloat162_rn(w0, w1);
                __nv_bfloat162 h23 = __floats2bfloat162_rn(w2, w3);
                float2 f01 = __bfloat1622float2(h01);
                float2 f23 = __bfloat1622float2(h23);
                __nv_bfloat162 g01 = __floats2bfloat162_rn(w0 - f01.x, w1 - f01.y);
                __nv_bfloat162 g23 = __floats2bfloat162_rn(w2 - f23.x, w3 - f23.y);
                whi[ks][half * 2]     = bf2u(h01);
                whi[ks][half * 2 + 1] = bf2u(h23);
                wlo[ks][half * 2]     = bf2u(g01);
                wlo[ks][half * 2 + 1] = bf2u(g23);
            }
        }
        // W lives entirely in this warp's registers, already in A-fragment layout.

        // ---- GEMM2: acc2 += W . Xj  (Whi*Xhi + Whi*Xlo + Wlo*Xhi) ----
        #pragma unroll
        for (int ks = 0; ks < 8; ++ks) {
            #pragma unroll
            for (int dp = 0; dp < 8; ++dp) {
                uint32_t bh[4], bl[4];
                ldsm4t(bh, sb + OFF_XJH + offB2 + ks * (16 * RSB) + dp * 32);
                ldsm4t(bl, sb + OFF_XJL + offB2 + ks * (16 * RSB) + dp * 32);
                mma16816(acc2[2 * dp],     whi[ks], bh[0], bh[1]);
                mma16816(acc2[2 * dp],     whi[ks], bl[0], bl[1]);
                mma16816(acc2[2 * dp],     wlo[ks], bh[0], bh[1]);
                mma16816(acc2[2 * dp + 1], whi[ks], bh[2], bh[3]);
                mma16816(acc2[2 * dp + 1], whi[ks], bl[2], bl[3]);
                mma16816(acc2[2 * dp + 1], wlo[ks], bh[2], bh[3]);
            }
        }
    }

    // ---- write out (scale 1/1024), float2 per fragment pair ----
    const float sc = 1.0f / (float)BLK;
    const size_t r0 = rowbase + (size_t)isub * 128 + 16 * wid + (l >> 2);
    float* o0 = out + r0 * D + (l & 3) * 2;
    float* o1 = out + (r0 + 8) * D + (l & 3) * 2;
    #pragma unroll
    for (int nt = 0; nt < 16; ++nt) {
        *(float2*)(o0 + nt * 8) = make_float2(acc2[nt][0] * sc, acc2[nt][1] * sc);
        *(float2*)(o1 + nt * 8) = make_float2(acc2[nt][2] * sc, acc2[nt][3] * sc);
    }
}

// ---------------------------------------------------------------------------
extern "C" void kernel_launch(void* const* d_in, const int* in_sizes, int n_in,
                              void* d_out, int out_size) {
    const float* x = (const float*)d_in[0];
    float* out = (float*)d_out;
    const int nrows = in_sizes[0] / D;

    static bool attr_set = false;
    if (!attr_set) {
        cudaFuncSetAttribute(attn_kernel,
                             cudaFuncAttributeMaxDynamicSharedMemorySize, SM_TOTAL);
        attr_set = true;
    }
    attn_kernel<<<nrows / 128, THREADS, SM_TOTAL>>>(x, out);
}

// round 5
// speedup vs baseline: 3.9869x; 1.1049x over previous
#include <cuda_runtime.h>
#include <cuda_bf16.h>
#include <cstdint>

#define D        128
#define BLK      1024
#define THREADS  256
#define INVC     (1.0f / 25.6f)

#define RSB      272                     // smem row stride bytes (136 bf16), LDSM conflict-free
#define OFF_SQI  0
#define OFF_SQJ  512
#define OFF_W    1024                    // 128 x RSB  (whi bf16 tile)
#define OFF_XIH  (OFF_W   + 128 * RSB)
#define OFF_XIL  (OFF_XIH + 128 * RSB)
#define OFF_XJH  (OFF_XIL + 128 * RSB)
#define OFF_XJL  (OFF_XJH + 128 * RSB)
#define SM_TOTAL (OFF_XJL + 128 * RSB)   // 175104 B

// ---------------- PTX helpers (base ISA only) ----------------
__device__ __forceinline__ uint32_t smem_u32(const void* p) {
    uint32_t a;
    asm("{ .reg .u64 t; cvta.to.shared.u64 t, %1; cvt.u32.u64 %0, t; }" : "=r"(a) : "l"(p));
    return a;
}
__device__ __forceinline__ void ldsm4(uint32_t r[4], uint32_t addr) {
    asm volatile("ldmatrix.sync.aligned.m8n8.x4.shared.b16 {%0,%1,%2,%3}, [%4];"
                 : "=r"(r[0]), "=r"(r[1]), "=r"(r[2]), "=r"(r[3]) : "r"(addr));
}
__device__ __forceinline__ void ldsm4t(uint32_t r[4], uint32_t addr) {
    asm volatile("ldmatrix.sync.aligned.m8n8.x4.trans.shared.b16 {%0,%1,%2,%3}, [%4];"
                 : "=r"(r[0]), "=r"(r[1]), "=r"(r[2]), "=r"(r[3]) : "r"(addr));
}
__device__ __forceinline__ void mma16816(float c[4], const uint32_t a[4],
                                         uint32_t b0, uint32_t b1) {
    asm volatile("mma.sync.aligned.m16n8k16.row.col.f32.bf16.bf16.f32 "
                 "{%0,%1,%2,%3}, {%4,%5,%6,%7}, {%8,%9}, {%0,%1,%2,%3};"
                 : "+f"(c[0]), "+f"(c[1]), "+f"(c[2]), "+f"(c[3])
                 : "r"(a[0]), "r"(a[1]), "r"(a[2]), "r"(a[3]), "r"(b0), "r"(b1));
}
__device__ __forceinline__ uint32_t bf2u(__nv_bfloat162 h) {
    return *reinterpret_cast<uint32_t*>(&h);
}

// ---------------------------------------------------------------------------
// Load one 128x128 fp32 tile -> bf16 hi/lo smem tiles + per-row sq norms.
// Warp w owns rows [16w, 16w+16); lane l owns cols [4l, 4l+4).
// ---------------------------------------------------------------------------
__device__ __forceinline__ void load_tile(const float4* __restrict__ src,
                                          char* hiT, char* loT, float* sqv,
                                          int wid, int l) {
    #pragma unroll
    for (int rr = 0; rr < 16; ++rr) {
        int row = wid * 16 + rr;
        float4 v = __ldg(&src[row * 32 + l]);
        float s = v.x * v.x + v.y * v.y + v.z * v.z + v.w * v.w;
        #pragma unroll
        for (int o = 16; o; o >>= 1) s += __shfl_xor_sync(0xFFFFFFFFu, s, o);
        if (l == 0) sqv[row] = s;
        __nv_bfloat162 h01 = __floats2bfloat162_rn(v.x, v.y);
        __nv_bfloat162 h23 = __floats2bfloat162_rn(v.z, v.w);
        float2 f01 = __bfloat1622float2(h01);
        float2 f23 = __bfloat1622float2(h23);
        __nv_bfloat162 g01 = __floats2bfloat162_rn(v.x - f01.x, v.y - f01.y);
        __nv_bfloat162 g23 = __floats2bfloat162_rn(v.z - f23.x, v.w - f23.y);
        *(uint2*)(hiT + row * RSB + l * 8) = make_uint2(bf2u(h01), bf2u(h23));
        *(uint2*)(loT + row * RSB + l * 8) = make_uint2(bf2u(g01), bf2u(g23));
    }
}

// ---------------------------------------------------------------------------
// Fused block self-attention. 2-D warp tiling:
//   GEMM1: warps (wm 0..3) x (wn 0..1): 32 M-rows x 64 N(j)-cols each.
//   W exchanged via smem (whi bf16 only).
//   GEMM2: warps (wm) x (wd=wn): 32 M-rows x 64 D-cols each; 2 combos.
// ---------------------------------------------------------------------------
__global__ __launch_bounds__(THREADS, 1)
void attn_kernel(const float* __restrict__ x, float* __restrict__ out) {
    extern __shared__ char sm[];
    const uint32_t sb = smem_u32(sm);
    float* sqi = (float*)(sm + OFF_SQI);
    float* sqj = (float*)(sm + OFF_SQJ);

    const int tid = threadIdx.x;
    const int wid = tid >> 5;
    const int l   = tid & 31;
    const int wm  = wid >> 1;        // M group (0..3): rows [32wm, 32wm+32)
    const int wn  = wid & 1;         // N/D group (0..1): cols [64wn, 64wn+64)
    const int cta  = blockIdx.x;
    const int blkI = cta >> 3, isub = cta & 7;
    const size_t rowbase = (size_t)blkI * BLK;

    // ldmatrix lane address patterns
    const int rowA = (l & 15);              // A-style / trans-B-style
    const int colA = (l >> 4);
    const int rowB = (l & 7) + ((l >> 4) << 3);   // non-trans B-style
    const int colB = (l >> 3) & 1;

    const uint32_t aoff  = (uint32_t)((32 * wm + rowA) * RSB + colA * 16);   // Xi / W A base (+16*RSB per mt)
    const uint32_t b1off = (uint32_t)((64 * wn + rowB) * RSB + colB * 16);   // G1 B base (+16*RSB per nt2)
    const uint32_t b2off = (uint32_t)(rowA * RSB + colA * 16 + 128 * wn);    // G2 B base (+16*RSB per ks, +32 per dp)

    // ---- Xi tile + sqi (once) ----
    load_tile((const float4*)(x + (rowbase + (size_t)isub * 128) * D),
              sm + OFF_XIH, sm + OFF_XIL, sqi, wid, l);
    __syncthreads();
    float sqiv[2][2];
    #pragma unroll
    for (int mt = 0; mt < 2; ++mt) {
        sqiv[mt][0] = sqi[32 * wm + 16 * mt + (l >> 2)];
        sqiv[mt][1] = sqi[32 * wm + 16 * mt + (l >> 2) + 8];
    }

    float acc2[2][8][4];
    #pragma unroll
    for (int mt = 0; mt < 2; ++mt)
        #pragma unroll
        for (int nt = 0; nt < 8; ++nt)
            #pragma unroll
            for (int c = 0; c < 4; ++c) acc2[mt][nt][c] = 0.0f;

    for (int jt = 0; jt < 8; ++jt) {
        __syncthreads();   // prev tile's Xj/W readers done
        load_tile((const float4*)(x + (rowbase + (size_t)jt * 128) * D),
                  sm + OFF_XJH, sm + OFF_XJL, sqj, wid, l);
        __syncthreads();

        // ---- GEMM1: S(32x64) = Xi . Xj^T, 3 bf16 combos ----
        float acc1[2][8][4];
        #pragma unroll
        for (int mt = 0; mt < 2; ++mt)
            #pragma unroll
            for (int nt = 0; nt < 8; ++nt)
                #pragma unroll
                for (int c = 0; c < 4; ++c) acc1[mt][nt][c] = 0.0f;

        #pragma unroll
        for (int ks = 0; ks < 8; ++ks) {
            uint32_t ah[2][4], al[2][4];
            #pragma unroll
            for (int mt = 0; mt < 2; ++mt) {
                ldsm4(ah[mt], sb + OFF_XIH + aoff + mt * (16 * RSB) + ks * 32);
                ldsm4(al[mt], sb + OFF_XIL + aoff + mt * (16 * RSB) + ks * 32);
            }
            #pragma unroll
            for (int nt2 = 0; nt2 < 4; ++nt2) {
                uint32_t bh[4], bl[4];
                ldsm4(bh, sb + OFF_XJH + b1off + nt2 * (16 * RSB) + ks * 32);
                ldsm4(bl, sb + OFF_XJL + b1off + nt2 * (16 * RSB) + ks * 32);
                #pragma unroll
                for (int mt = 0; mt < 2; ++mt) {
                    mma16816(acc1[mt][2 * nt2],     ah[mt], bh[0], bh[1]);
                    mma16816(acc1[mt][2 * nt2 + 1], ah[mt], bh[2], bh[3]);
                    mma16816(acc1[mt][2 * nt2],     al[mt], bh[0], bh[1]);
                    mma16816(acc1[mt][2 * nt2 + 1], al[mt], bh[2], bh[3]);
                    mma16816(acc1[mt][2 * nt2],     ah[mt], bl[0], bl[1]);
                    mma16816(acc1[mt][2 * nt2 + 1], ah[mt], bl[2], bl[3]);
                }
            }
        }

        // ---- epilogue: w = exp(-max(d2,0)/25.6), whi -> smem W tile ----
        #pragma unroll
        for (int nt = 0; nt < 8; ++nt) {
            float2 sj = *(float2*)&sqj[64 * wn + 8 * nt + 2 * (l & 3)];
            #pragma unroll
            for (int mt = 0; mt < 2; ++mt) {
                const float* c = acc1[mt][nt];
                float w0 = __expf(-fmaxf(sqiv[mt][0] + sj.x - 2.0f * c[0], 0.0f) * INVC);
                float w1 = __expf(-fmaxf(sqiv[mt][0] + sj.y - 2.0f * c[1], 0.0f) * INVC);
                float w2 = __expf(-fmaxf(sqiv[mt][1] + sj.x - 2.0f * c[2], 0.0f) * INVC);
                float w3 = __expf(-fmaxf(sqiv[mt][1] + sj.y - 2.0f * c[3], 0.0f) * INVC);
                uint32_t h01 = bf2u(__floats2bfloat162_rn(w0, w1));
                uint32_t h23 = bf2u(__floats2bfloat162_rn(w2, w3));
                uint32_t wa = (uint32_t)((32 * wm + 16 * mt + (l >> 2)) * RSB
                                         + (64 * wn + 8 * nt + 2 * (l & 3)) * 2);
                *(uint32_t*)(sm + OFF_W + wa)           = h01;
                *(uint32_t*)(sm + OFF_W + wa + 8 * RSB) = h23;
            }
        }
        __syncthreads();   // W tile complete, visible to all warps

        // ---- GEMM2: acc2(32x64) += W . Xj  (Whi*Xhi + Whi*Xlo) ----
        #pragma unroll
        for (int ks = 0; ks < 8; ++ks) {
            uint32_t wh[2][4];
            #pragma unroll
            for (int mt = 0; mt < 2; ++mt)
                ldsm4(wh[mt], sb + OFF_W + aoff + mt * (16 * RSB) + ks * 32);
            #pragma unroll
            for (int dp = 0; dp < 4; ++dp) {
                uint32_t bh[4], bl[4];
                ldsm4t(bh, sb + OFF_XJH + b2off + ks * (16 * RSB) + dp * 32);
                ldsm4t(bl, sb + OFF_XJL + b2off + ks * (16 * RSB) + dp * 32);
                #pragma unroll
                for (int mt = 0; mt < 2; ++mt) {
                    mma16816(acc2[mt][2 * dp],     wh[mt], bh[0], bh[1]);
                    mma16816(acc2[mt][2 * dp + 1], wh[mt], bh[2], bh[3]);
                    mma16816(acc2[mt][2 * dp],     wh[mt], bl[0], bl[1]);
                    mma16816(acc2[mt][2 * dp + 1], wh[mt], bl[2], bl[3]);
                }
            }
        }
    }

    // ---- write out (scale 1/1024) ----
    const float sc = 1.0f / (float)BLK;
    #pragma unroll
    for (int mt = 0; mt < 2; ++mt) {
        const size_t r0 = rowbase + (size_t)isub * 128 + 32 * wm + 16 * mt + (l >> 2);
        #pragma unroll
        for (int nt = 0; nt < 8; ++nt) {
            const int col = 64 * wn + 8 * nt + 2 * (l & 3);
            *(float2*)(out + r0 * D + col)       = make_float2(acc2[mt][nt][0] * sc, acc2[mt][nt][1] * sc);
            *(float2*)(out + (r0 + 8) * D + col) = make_float2(acc2[mt][nt][2] * sc, acc2[mt][nt][3] * sc);
        }
    }
}

// ---------------------------------------------------------------------------
extern "C" void kernel_launch(void* const* d_in, const int* in_sizes, int n_in,
                              void* d_out, int out_size) {
    const float* x = (const float*)d_in[0];
    float* out = (float*)d_out;
    const int nrows = in_sizes[0] / D;

    static bool attr_set = false;
    if (!attr_set) {
        cudaFuncSetAttribute(attn_kernel,
                             cudaFuncAttributeMaxDynamicSharedMemorySize, SM_TOTAL);
        attr_set = true;
    }
    attn_kernel<<<nrows / 128, THREADS, SM_TOTAL>>>(x, out);
}

// round 7
// speedup vs baseline: 4.1567x; 1.0426x over previous
#include <cuda_runtime.h>
#include <cuda_bf16.h>
#include <cstdint>

#define D        128
#define BLK      1024
#define THREADS  256
#define NROWS    262144

// exponent constants: w = exp(-max(d2,0)/25.6), d2 = sqi+sqj-2S
//   -d2/25.6*log2e = S*C2 + ci + cj,  ci = -sqi*log2e/25.6 (pre-scaled in prep)
#define C2       0.11271055f          // 2*log2e/25.6
#define SQSCALE  (-0.056355275f)      // -log2e/25.6

#define RSB      272                  // padded smem row stride bytes (R5-proven)
#define OFF_SQI  0
#define OFF_SQJ  512
#define OFF_W    1024                 // 128 x RSB  (whi bf16 tile)
#define OFF_XIH  (OFF_W   + 128 * RSB)
#define OFF_XIL  (OFF_XIH + 128 * RSB)
#define OFF_XJH  (OFF_XIL + 128 * RSB)
#define OFF_XJL  (OFF_XJH + 128 * RSB)
#define SM_TOTAL (OFF_XJL + 128 * RSB)   // 175104 B

// ---------------- global scratch ----------------
__device__ float          g_sq[NROWS];                 // pre-scaled: -||x||^2*log2e/25.6
__device__ __nv_bfloat16  g_xhi[(size_t)NROWS * D];
__device__ __nv_bfloat16  g_xlo[(size_t)NROWS * D];

// ---------------- PTX helpers (base ISA only) ----------------
__device__ __forceinline__ uint32_t smem_u32(const void* p) {
    uint32_t a;
    asm("{ .reg .u64 t; cvta.to.shared.u64 t, %1; cvt.u32.u64 %0, t; }" : "=r"(a) : "l"(p));
    return a;
}
__device__ __forceinline__ void ldsm4(uint32_t r[4], uint32_t addr) {
    asm volatile("ldmatrix.sync.aligned.m8n8.x4.shared.b16 {%0,%1,%2,%3}, [%4];"
                 : "=r"(r[0]), "=r"(r[1]), "=r"(r[2]), "=r"(r[3]) : "r"(addr));
}
__device__ __forceinline__ void ldsm4t(uint32_t r[4], uint32_t addr) {
    asm volatile("ldmatrix.sync.aligned.m8n8.x4.trans.shared.b16 {%0,%1,%2,%3}, [%4];"
                 : "=r"(r[0]), "=r"(r[1]), "=r"(r[2]), "=r"(r[3]) : "r"(addr));
}
__device__ __forceinline__ void mma16816(float c[4], const uint32_t a[4],
                                         uint32_t b0, uint32_t b1) {
    asm volatile("mma.sync.aligned.m16n8k16.row.col.f32.bf16.bf16.f32 "
                 "{%0,%1,%2,%3}, {%4,%5,%6,%7}, {%8,%9}, {%0,%1,%2,%3};"
                 : "+f"(c[0]), "+f"(c[1]), "+f"(c[2]), "+f"(c[3])
                 : "r"(a[0]), "r"(a[1]), "r"(a[2]), "r"(a[3]), "r"(b0), "r"(b1));
}
__device__ __forceinline__ float ex2(float e) {
    float r;
    asm("ex2.approx.f32 %0, %1;" : "=f"(r) : "f"(e));
    return r;
}
__device__ __forceinline__ uint32_t bf2u(__nv_bfloat162 h) {
    return *reinterpret_cast<uint32_t*>(&h);
}

// ---------------------------------------------------------------------------
// Prepass: fp32 -> bf16 hi/lo + pre-scaled row norms. One warp per row.
// ---------------------------------------------------------------------------
__global__ __launch_bounds__(256) void prep_kernel(const float4* __restrict__ x) {
    int row = blockIdx.x * 8 + (threadIdx.x >> 5);
    int l   = threadIdx.x & 31;
    float4 v = __ldg(&x[(size_t)row * 32 + l]);
    float s = v.x * v.x + v.y * v.y + v.z * v.z + v.w * v.w;
    #pragma unroll
    for (int o = 16; o; o >>= 1) s += __shfl_xor_sync(0xFFFFFFFFu, s, o);
    if (l == 0) g_sq[row] = s * SQSCALE;
    __nv_bfloat162 h01 = __floats2bfloat162_rn(v.x, v.y);
    __nv_bfloat162 h23 = __floats2bfloat162_rn(v.z, v.w);
    float2 f01 = __bfloat1622float2(h01);
    float2 f23 = __bfloat1622float2(h23);
    __nv_bfloat162 g01 = __floats2bfloat162_rn(v.x - f01.x, v.y - f01.y);
    __nv_bfloat162 g23 = __floats2bfloat162_rn(v.z - f23.x, v.w - f23.y);
    ((uint2*)g_xhi)[(size_t)row * 32 + l] = make_uint2(bf2u(h01), bf2u(h23));
    ((uint2*)g_xlo)[(size_t)row * 32 + l] = make_uint2(bf2u(g01), bf2u(g23));
}

// Load one pre-split 128x128 bf16 tile pair into padded smem (R5 layout).
__device__ __forceinline__ void load_bf_tile(char* dh, char* dl,
                                             const uint4* __restrict__ gh,
                                             const uint4* __restrict__ gl, int tid) {
    #pragma unroll
    for (int it = 0; it < 8; ++it) {
        int q   = tid + it * 256;          // 0..2047 16B chunks
        int row = q >> 4, c16 = q & 15;
        uint4 vh = __ldg(gh + q);
        uint4 vl = __ldg(gl + q);
        *(uint4*)(dh + row * RSB + c16 * 16) = vh;
        *(uint4*)(dl + row * RSB + c16 * 16) = vl;
    }
}

// ---------------------------------------------------------------------------
// Fused block self-attention (R5-proven body, prepass-fed).
// ---------------------------------------------------------------------------
__global__ __launch_bounds__(THREADS, 1)
void attn_kernel(float* __restrict__ out) {
    extern __shared__ char sm[];
    const uint32_t sb = smem_u32(sm);
    float* sqi = (float*)(sm + OFF_SQI);
    float* sqj = (float*)(sm + OFF_SQJ);

    const int tid = threadIdx.x;
    const int wid = tid >> 5;
    const int l   = tid & 31;
    const int wm  = wid >> 1;        // 0..3: rows [32wm, 32wm+32)
    const int wn  = wid & 1;         // 0..1: cols [64wn, 64wn+64)
    const int cta  = blockIdx.x;
    const int blkI = cta >> 3, isub = cta & 7;
    const size_t rowbase = (size_t)blkI * BLK;

    // ldmatrix lane address patterns (identical to R5)
    const int rowA = (l & 15);
    const int colA = (l >> 4);
    const int rowB = (l & 7) + ((l >> 4) << 3);
    const int colB = (l >> 3) & 1;

    const uint32_t aoff  = (uint32_t)((32 * wm + rowA) * RSB + colA * 16);
    const uint32_t b1off = (uint32_t)((64 * wn + rowB) * RSB + colB * 16);
    const uint32_t b2off = (uint32_t)(rowA * RSB + colA * 16 + 128 * wn);

    // ---- Xi tiles + sqi (once) ----
    load_bf_tile(sm + OFF_XIH, sm + OFF_XIL,
                 (const uint4*)(g_xhi + (rowbase + (size_t)isub * 128) * D),
                 (const uint4*)(g_xlo + (rowbase + (size_t)isub * 128) * D), tid);
    if (tid < 128) sqi[tid] = g_sq[rowbase + isub * 128 + tid];
    __syncthreads();
    float civ[2][2];
    #pragma unroll
    for (int mt = 0; mt < 2; ++mt) {
        civ[mt][0] = sqi[32 * wm + 16 * mt + (l >> 2)];
        civ[mt][1] = sqi[32 * wm + 16 * mt + (l >> 2) + 8];
    }

    float acc2[2][8][4];
    #pragma unroll
    for (int mt = 0; mt < 2; ++mt)
        #pragma unroll
        for (int nt = 0; nt < 8; ++nt)
            #pragma unroll
            for (int c = 0; c < 4; ++c) acc2[mt][nt][c] = 0.0f;

    for (int jt = 0; jt < 8; ++jt) {
        __syncthreads();   // prev tile's Xj/W readers done
        load_bf_tile(sm + OFF_XJH, sm + OFF_XJL,
                     (const uint4*)(g_xhi + (rowbase + (size_t)jt * 128) * D),
                     (const uint4*)(g_xlo + (rowbase + (size_t)jt * 128) * D), tid);
        if (tid < 128) sqj[tid] = g_sq[rowbase + jt * 128 + tid];
        __syncthreads();

        // ---- GEMM1: S(32x64) = Xi . Xj^T, 3 bf16 combos ----
        float acc1[2][8][4];
        #pragma unroll
        for (int mt = 0; mt < 2; ++mt)
            #pragma unroll
            for (int nt = 0; nt < 8; ++nt)
                #pragma unroll
                for (int c = 0; c < 4; ++c) acc1[mt][nt][c] = 0.0f;

        #pragma unroll
        for (int ks = 0; ks < 8; ++ks) {
            uint32_t ah[2][4], al[2][4];
            #pragma unroll
            for (int mt = 0; mt < 2; ++mt) {
                ldsm4(ah[mt], sb + OFF_XIH + aoff + mt * (16 * RSB) + ks * 32);
                ldsm4(al[mt], sb + OFF_XIL + aoff + mt * (16 * RSB) + ks * 32);
            }
            #pragma unroll
            for (int nt2 = 0; nt2 < 4; ++nt2) {
                uint32_t bh[4], bl[4];
                ldsm4(bh, sb + OFF_XJH + b1off + nt2 * (16 * RSB) + ks * 32);
                ldsm4(bl, sb + OFF_XJL + b1off + nt2 * (16 * RSB) + ks * 32);
                #pragma unroll
                for (int mt = 0; mt < 2; ++mt) {
                    mma16816(acc1[mt][2 * nt2],     ah[mt], bh[0], bh[1]);
                    mma16816(acc1[mt][2 * nt2 + 1], ah[mt], bh[2], bh[3]);
                    mma16816(acc1[mt][2 * nt2],     al[mt], bh[0], bh[1]);
                    mma16816(acc1[mt][2 * nt2 + 1], al[mt], bh[2], bh[3]);
                    mma16816(acc1[mt][2 * nt2],     ah[mt], bl[0], bl[1]);
                    mma16816(acc1[mt][2 * nt2 + 1], ah[mt], bl[2], bl[3]);
                }
            }
        }

        // ---- epilogue: w = ex2(min(S*C2 + ci + cj, 0)), whi -> smem W ----
        #pragma unroll
        for (int nt = 0; nt < 8; ++nt) {
            float2 cj = *(float2*)&sqj[64 * wn + 8 * nt + 2 * (l & 3)];
            #pragma unroll
            for (int mt = 0; mt < 2; ++mt) {
                const float* c = acc1[mt][nt];
                float b0 = civ[mt][0] + cj.x, b1 = civ[mt][0] + cj.y;
                float b2 = civ[mt][1] + cj.x, b3 = civ[mt][1] + cj.y;
                float w0 = ex2(fminf(fmaf(c[0], C2, b0), 0.0f));
                float w1 = ex2(fminf(fmaf(c[1], C2, b1), 0.0f));
                float w2 = ex2(fminf(fmaf(c[2], C2, b2), 0.0f));
                float w3 = ex2(fminf(fmaf(c[3], C2, b3), 0.0f));
                uint32_t h01 = bf2u(__floats2bfloat162_rn(w0, w1));
                uint32_t h23 = bf2u(__floats2bfloat162_rn(w2, w3));
                uint32_t wa = (uint32_t)((32 * wm + 16 * mt + (l >> 2)) * RSB
                                         + (64 * wn + 8 * nt + 2 * (l & 3)) * 2);
                *(uint32_t*)(sm + OFF_W + wa)           = h01;
                *(uint32_t*)(sm + OFF_W + wa + 8 * RSB) = h23;
            }
        }
        __syncthreads();   // W tile complete

        // ---- GEMM2: acc2(32x64) += W . Xj  (Whi*Xhi + Whi*Xlo) ----
        #pragma unroll
        for (int ks = 0; ks < 8; ++ks) {
            uint32_t wh[2][4];
            #pragma unroll
            for (int mt = 0; mt < 2; ++mt)
                ldsm4(wh[mt], sb + OFF_W + aoff + mt * (16 * RSB) + ks * 32);
            #pragma unroll
            for (int dp = 0; dp < 4; ++dp) {
                uint32_t bh[4], bl[4];
                ldsm4t(bh, sb + OFF_XJH + b2off + ks * (16 * RSB) + dp * 32);
                ldsm4t(bl, sb + OFF_XJL + b2off + ks * (16 * RSB) + dp * 32);
                #pragma unroll
                for (int mt = 0; mt < 2; ++mt) {
                    mma16816(acc2[mt][2 * dp],     wh[mt], bh[0], bh[1]);
                    mma16816(acc2[mt][2 * dp + 1], wh[mt], bh[2], bh[3]);
                    mma16816(acc2[mt][2 * dp],     wh[mt], bl[0], bl[1]);
                    mma16816(acc2[mt][2 * dp + 1], wh[mt], bl[2], bl[3]);
                }
            }
        }
    }

    // ---- write out (scale 1/1024) ----
    const float sc = 1.0f / (float)BLK;
    #pragma unroll
    for (int mt = 0; mt < 2; ++mt) {
        const size_t r0 = rowbase + (size_t)isub * 128 + 32 * wm + 16 * mt + (l >> 2);
        #pragma unroll
        for (int nt = 0; nt < 8; ++nt) {
            const int col = 64 * wn + 8 * nt + 2 * (l & 3);
            *(float2*)(out + r0 * D + col)       = make_float2(acc2[mt][nt][0] * sc, acc2[mt][nt][1] * sc);
            *(float2*)(out + (r0 + 8) * D + col) = make_float2(acc2[mt][nt][2] * sc, acc2[mt][nt][3] * sc);
        }
    }
}

// ---------------------------------------------------------------------------
extern "C" void kernel_launch(void* const* d_in, const int* in_sizes, int n_in,
                              void* d_out, int out_size) {
    const float* x = (const float*)d_in[0];
    float* out = (float*)d_out;
    const int nrows = in_sizes[0] / D;

    static bool attr_set = false;
    if (!attr_set) {
        cudaFuncSetAttribute(attn_kernel,
                             cudaFuncAttributeMaxDynamicSharedMemorySize, SM_TOTAL);
        attr_set = true;
    }
    prep_kernel<<<nrows / 8, 256>>>((const float4*)x);
    attn_kernel<<<nrows / 128, THREADS, SM_TOTAL>>>(out);
}